// round 10
// baseline (speedup 1.0000x reference)
#include <cuda_runtime.h>
#include <cuda_fp16.h>

// HashGridEncoder2D: L=16, F=2, N=1048576, T=524288. fp16 tables scaled by 4096.
// R10: scatter with folded binbase (no random binbase gathers), 4 pts/thread;
// main kernel drops the uv-staging barrier (direct broadcast loads).
// 64x64-bin aggregated counting sort; repack fused into hist launch.

#define NPTS    1048576
#define TSIZE   524288
#define TMASK   (TSIZE - 1)
#define HPRIME  131101
#define QTOTAL  659835                 // sum of res^2 over dense levels 0..11
#define HBASE   663817                 // float2 index where hashed tables start
#define RPTOTAL (QTOTAL + TSIZE)
#define RPBLK   ((RPTOTAL + 255) / 256)
#define NBINS   4096
#define HISTBLK 256                    // hist blocks (4096 points each)
#define SCTBLK  256                    // scatter blocks (4096 points each)
#define SCALE_F     4096.0f
#define INV_SCALE_F (1.0f / 4096.0f)

__constant__ int c_res[16] = {16, 22, 30, 42, 58, 80, 111, 153,
                              212, 294, 406, 561, 776, 1072, 1482, 2048};
__constant__ int c_off[16] = {0, 289, 818, 1779, 3628, 7109, 13670, 26214,
                              49930, 95299, 182324, 347973,
                              663817, 1188105, 1712393, 2236681};
__constant__ int c_qoff[12] = {0, 256, 740, 1640, 3404, 6768, 13168,
                               25489, 48898, 93842, 180278, 345114};

// 10.6 MB: dense cell (l,x,y) -> {v00,v01,v10,v11} as 4 half2 (16B aligned).
__device__ __align__(16) __half2 g_qh[(size_t)QTOTAL * 4];
// 8.4 MB: 16B-aligned fp16 mirror of the 4 hashed level tables.
__device__ __align__(16) __half2 g_hh[4 * TSIZE];

// bucketing state (rebuilt every replay)
__device__ int    g_hist[NBINS];
__device__ int    g_binbase[NBINS];
__device__ int    g_fill[NBINS];
__device__ __align__(16) float4 g_uvp[NPTS];   // {u, v, perm-as-int, 0}

__device__ __forceinline__ __half2 sc_h2(float2 v) {
    return __floats2half2_rn(v.x * SCALE_F, v.y * SCALE_F);
}

__device__ __forceinline__ int bin_of(float px, float py) {
    int kx = min((int)(px * 64.0f), 63);
    int ky = min((int)(py * 64.0f), 63);
    return ky * 64 + kx;
}

__global__ void zero_kernel() {
    g_hist[blockIdx.x * blockDim.x + threadIdx.x] = 0;
}

// Fused: blocks [0, HISTBLK) build the histogram, blocks [HISTBLK, ...) repack tables.
__global__ void __launch_bounds__(256)
hist_repack_kernel(const float2* __restrict__ uv, const float2* __restrict__ lat)
{
    if (blockIdx.x < HISTBLK) {
        __shared__ int s_h[NBINS];
        int tid = threadIdx.x;
#pragma unroll
        for (int i = 0; i < NBINS / 256; i++) s_h[tid + i * 256] = 0;
        __syncthreads();

        const float4* uv4 = (const float4*)uv;   // 2 points per float4
        int base4 = blockIdx.x * 2048;           // 4096 points per block
#pragma unroll
        for (int i = 0; i < 8; i++) {
            float4 q = __ldg(&uv4[base4 + i * 256 + tid]);
            atomicAdd(&s_h[bin_of(q.x, q.y)], 1);
            atomicAdd(&s_h[bin_of(q.z, q.w)], 1);
        }
        __syncthreads();

#pragma unroll
        for (int i = 0; i < NBINS / 256; i++) {
            int b = tid + i * 256;
            int c = s_h[b];
            if (c) atomicAdd(&g_hist[b], c);
        }
        return;
    }

    int c = (blockIdx.x - HISTBLK) * 256 + threadIdx.x;
    if (c >= RPTOTAL) return;

    if (c >= QTOTAL) {
        int base = (c - QTOTAL) * 4;
        __half2 h0 = sc_h2(lat[HBASE + base + 0]);
        __half2 h1 = sc_h2(lat[HBASE + base + 1]);
        __half2 h2 = sc_h2(lat[HBASE + base + 2]);
        __half2 h3 = sc_h2(lat[HBASE + base + 3]);
        float4 v;
        ((__half2*)&v)[0] = h0; ((__half2*)&v)[1] = h1;
        ((__half2*)&v)[2] = h2; ((__half2*)&v)[3] = h3;
        *(float4*)(g_hh + base) = v;
        return;
    }

    int l = 0;
#pragma unroll
    for (int i = 1; i < 12; i++) l += (c >= c_qoff[i]);

    int local = c - c_qoff[l];
    int res   = c_res[l];
    int x     = local / res;
    int y     = local - x * res;
    int base  = c_off[l] + x * res + y;

    __half2 h00 = sc_h2(lat[base]);
    __half2 h01 = sc_h2(lat[base + 1]);
    __half2 h10 = sc_h2(lat[base + res]);
    __half2 h11 = sc_h2(lat[base + res + 1]);

    float4 v;
    ((__half2*)&v)[0] = h00; ((__half2*)&v)[1] = h01;
    ((__half2*)&v)[2] = h10; ((__half2*)&v)[3] = h11;
    *(float4*)(g_qh + (size_t)c * 4) = v;
}

// 4096-bin exclusive scan (1024 threads, 4 bins each) + zero g_fill.
__global__ void __launch_bounds__(1024)
scan_kernel() {
    __shared__ int s[1024];
    int t = threadIdx.x;
    int v0 = g_hist[4 * t + 0];
    int v1 = g_hist[4 * t + 1];
    int v2 = g_hist[4 * t + 2];
    int v3 = g_hist[4 * t + 3];
    int sum = v0 + v1 + v2 + v3;
    s[t] = sum;
    __syncthreads();
#pragma unroll
    for (int off = 1; off < 1024; off <<= 1) {
        int v = (t >= off) ? s[t - off] : 0;
        __syncthreads();
        s[t] += v;
        __syncthreads();
    }
    int excl = s[t] - sum;
    g_binbase[4 * t + 0] = excl;
    g_binbase[4 * t + 1] = excl + v0;
    g_binbase[4 * t + 2] = excl + v0 + v1;
    g_binbase[4 * t + 3] = excl + v0 + v1 + v2;
    g_fill[4 * t + 0] = 0;
    g_fill[4 * t + 1] = 0;
    g_fill[4 * t + 2] = 0;
    g_fill[4 * t + 3] = 0;
}

// 256 blocks x 1024 threads x 4 points: smem ranks, then s_off[b] =
// binbase[b] (coalesced) + aggregated global fill -> one 16B store per point.
__global__ void __launch_bounds__(1024)
scatter_kernel(const float2* __restrict__ uv)
{
    __shared__ int s_cnt[NBINS];
    __shared__ int s_off[NBINS];
    int tid = threadIdx.x;
#pragma unroll
    for (int i = 0; i < NBINS / 1024; i++) s_cnt[tid + i * 1024] = 0;
    __syncthreads();

    const float4* uv4 = (const float4*)uv;
    int base4 = blockIdx.x * 2048;           // 4096 points per block
    float4 qa = __ldg(&uv4[base4 + tid]);
    float4 qb = __ldg(&uv4[base4 + 1024 + tid]);

    int b0 = bin_of(qa.x, qa.y);
    int b1 = bin_of(qa.z, qa.w);
    int b2 = bin_of(qb.x, qb.y);
    int b3 = bin_of(qb.z, qb.w);
    int r0 = atomicAdd(&s_cnt[b0], 1);
    int r1 = atomicAdd(&s_cnt[b1], 1);
    int r2 = atomicAdd(&s_cnt[b2], 1);
    int r3 = atomicAdd(&s_cnt[b3], 1);
    __syncthreads();

#pragma unroll
    for (int i = 0; i < NBINS / 1024; i++) {
        int b = tid + i * 1024;
        int c = s_cnt[b];
        int f = c ? atomicAdd(&g_fill[b], c) : 0;
        s_off[b] = g_binbase[b] + f;           // coalesced binbase read
    }
    __syncthreads();

    int na = (base4 + tid) * 2;
    int nb = (base4 + 1024 + tid) * 2;
    g_uvp[s_off[b0] + r0] = make_float4(qa.x, qa.y, __int_as_float(na), 0.0f);
    g_uvp[s_off[b1] + r1] = make_float4(qa.z, qa.w, __int_as_float(na + 1), 0.0f);
    g_uvp[s_off[b2] + r2] = make_float4(qb.x, qb.y, __int_as_float(nb), 0.0f);
    g_uvp[s_off[b3] + r3] = make_float4(qb.z, qb.w, __int_as_float(nb + 1), 0.0f);
}

__global__ void __launch_bounds__(256)
hashgrid2d_kernel(float4* __restrict__ out)
{
    __shared__ float4 s_tr[256];

    int tid = threadIdx.x;
    int w   = tid >> 5;          // slot: levels {2w, 2w+1}
    int ln  = tid & 31;
    int n0  = blockIdx.x * 32;

    // every warp loads the same 32 packed records (4 lines, L1 broadcast)
    float4 q = __ldg(&g_uvp[n0 + ln]);
    float2 p = make_float2(q.x, q.y);

    float r0, r1, r2, r3;

    if (w < 6) {
        // ---- two dense levels: one 16B quad load each ----
        float rr[4];
#pragma unroll
        for (int k = 0; k < 2; k++) {
            int l   = 2 * w + k;
            int res = c_res[l];

            float fres = (float)res;
            float sx = p.x * fres;
            float sy = p.y * fres;
            float fx = floorf(sx);
            float fy = floorf(sy);
            int   x0 = (int)fx;
            int   y0 = (int)fy;
            float px = sx - fx;
            float py = sy - fy;

            float4 raw = *(const float4*)(g_qh + (size_t)(c_qoff[l] + x0 * res + y0) * 4);
            const __half2* h = (const __half2*)&raw;
            float2 v00 = __half22float2(h[0]);
            float2 v01 = __half22float2(h[1]);
            float2 v10 = __half22float2(h[2]);
            float2 v11 = __half22float2(h[3]);

            float qx = 1.0f - px;
            float qy = 1.0f - py;
            float w00 = qx * qy;
            float w01 = qx * py;
            float w10 = px * qy;
            float w11 = px * py;

            rr[2 * k + 0] = v00.x * w00 + v01.x * w01 + v10.x * w10 + v11.x * w11;
            rr[2 * k + 1] = v00.y * w00 + v01.y * w01 + v10.y * w10 + v11.y * w11;
        }
        r0 = rr[0]; r1 = rr[1]; r2 = rr[2]; r3 = rr[3];
    } else {
        // ---- two hashed levels: 16B group-of-4 loads + weight scatter ----
        float rr[4];
#pragma unroll
        for (int k = 0; k < 2; k++) {
            int l = 12 + (w - 6) * 2 + k;

            float fres = (float)c_res[l];
            float sx = p.x * fres;
            float sy = p.y * fres;
            float fx = floorf(sx);
            float fy = floorf(sy);
            int   x0 = (int)fx;
            int   y0 = (int)fy;
            float px = sx - fx;
            float py = sy - fy;

            float qx = 1.0f - px;
            float qy = 1.0f - py;

            const __half2* H = g_hh + (size_t)(l - 12) * TSIZE;

            int hy0 = y0 * HPRIME;
            int hy1 = hy0 + HPRIME;
            int i0  = (x0 ^ hy0) & TMASK;
            int i1  = (x0 ^ hy1) & TMASK;

            float4 raw0 = *(const float4*)(H + (i0 & ~3));
            float4 raw1 = *(const float4*)(H + (i1 & ~3));
            const __half2* v0 = (const __half2*)&raw0;
            const __half2* v1 = (const __half2*)&raw1;

            int  d   = ((x0 + 1) ^ x0) & 3;        // 1 or 3
            bool ing = (x0 & 3) != 3;              // x0+1 in same 16B group?
            float wpx = ing ? px : 0.0f;

            int pA0 = i0 & 3, pB0 = pA0 ^ d;
            int pA1 = i1 & 3, pB1 = pA1 ^ d;

            float e0x = 0.f, e0y = 0.f, e1x = 0.f, e1y = 0.f;
#pragma unroll
            for (int t = 0; t < 4; t++) {
                float wt0 = (t == pA0) ? qx : ((t == pB0) ? wpx : 0.0f);
                float wt1 = (t == pA1) ? qx : ((t == pB1) ? wpx : 0.0f);
                float2 a = __half22float2(v0[t]);
                float2 b = __half22float2(v1[t]);
                e0x += wt0 * a.x; e0y += wt0 * a.y;
                e1x += wt1 * b.x; e1y += wt1 * b.y;
            }

            if (!ing) {
                int x1 = x0 + 1;
                float2 f0 = __half22float2(H[(x1 ^ hy0) & TMASK]);
                float2 f1 = __half22float2(H[(x1 ^ hy1) & TMASK]);
                e0x += px * f0.x; e0y += px * f0.y;
                e1x += px * f1.x; e1y += px * f1.y;
            }

            rr[2 * k + 0] = qy * e0x + py * e1x;
            rr[2 * k + 1] = qy * e0y + py * e1y;
        }
        r0 = rr[0]; r1 = rr[1]; r2 = rr[2]; r3 = rr[3];
    }

    r0 *= INV_SCALE_F; r1 *= INV_SCALE_F; r2 *= INV_SCALE_F; r3 *= INV_SCALE_F;

    // XOR-swizzled transpose; store to each point's ORIGINAL slot (one 128B
    // line per point -> same wavefront count as a coalesced store).
    s_tr[ln * 8 + (w ^ (ln & 7))] = make_float4(r0, r1, r2, r3);
    __syncthreads();

    int jj = tid & 7;
    int ll = tid >> 3;
    int pn = __float_as_int(__ldg(&g_uvp[n0 + ll].z));   // L1 hit
    out[(size_t)pn * 8 + jj] = s_tr[ll * 8 + (jj ^ (ll & 7))];
}

extern "C" void kernel_launch(void* const* d_in, const int* in_sizes, int n_in,
                              void* d_out, int out_size)
{
    const float2* uv  = (const float2*)d_in[0];
    const float2* lat = (const float2*)d_in[1];
    float4*       out = (float4*)d_out;

    zero_kernel<<<NBINS / 256, 256>>>();
    hist_repack_kernel<<<HISTBLK + RPBLK, 256>>>(uv, lat);
    scan_kernel<<<1, 1024>>>();
    scatter_kernel<<<SCTBLK, 1024>>>(uv);

    hashgrid2d_kernel<<<NPTS / 32, 256>>>(out);
}

// round 11
// speedup vs baseline: 1.0113x; 1.0113x over previous
#include <cuda_runtime.h>
#include <cuda_fp16.h>

// HashGridEncoder2D: L=16, F=2, N=1048576, T=524288. fp16 tables scaled by 4096.
// R11: 32x32-bin aggregated counting sort; scatter at 512thr x 512blk (3 blocks/SM
// resident -> latency hidden); main kernel = R9's staged slot-warp form.
// Dense levels: 16B quad LDG. Hashed: 16B group-of-4 + branchless weight scatter.

#define NPTS    1048576
#define TSIZE   524288
#define TMASK   (TSIZE - 1)
#define HPRIME  131101
#define QTOTAL  659835                 // sum of res^2 over dense levels 0..11
#define HBASE   663817                 // float2 index where hashed tables start
#define RPTOTAL (QTOTAL + TSIZE)
#define RPBLK   ((RPTOTAL + 255) / 256)
#define NBINS   1024
#define HISTBLK 256                    // hist blocks (4096 points each)
#define SCTBLK  512                    // scatter blocks (2048 points each)
#define SCALE_F     4096.0f
#define INV_SCALE_F (1.0f / 4096.0f)

__constant__ int c_res[16] = {16, 22, 30, 42, 58, 80, 111, 153,
                              212, 294, 406, 561, 776, 1072, 1482, 2048};
__constant__ int c_off[16] = {0, 289, 818, 1779, 3628, 7109, 13670, 26214,
                              49930, 95299, 182324, 347973,
                              663817, 1188105, 1712393, 2236681};
__constant__ int c_qoff[12] = {0, 256, 740, 1640, 3404, 6768, 13168,
                               25489, 48898, 93842, 180278, 345114};

// 10.6 MB: dense cell (l,x,y) -> {v00,v01,v10,v11} as 4 half2 (16B aligned).
__device__ __align__(16) __half2 g_qh[(size_t)QTOTAL * 4];
// 8.4 MB: 16B-aligned fp16 mirror of the 4 hashed level tables.
__device__ __align__(16) __half2 g_hh[4 * TSIZE];

// bucketing state (rebuilt every replay)
__device__ int    g_hist[NBINS];
__device__ int    g_binbase[NBINS];
__device__ int    g_fill[NBINS];
__device__ __align__(16) float4 g_uvp[NPTS];   // {u, v, perm-as-int, 0}

__device__ __forceinline__ __half2 sc_h2(float2 v) {
    return __floats2half2_rn(v.x * SCALE_F, v.y * SCALE_F);
}

__device__ __forceinline__ int bin_of(float px, float py) {
    int kx = min((int)(px * 32.0f), 31);
    int ky = min((int)(py * 32.0f), 31);
    return ky * 32 + kx;
}

__global__ void zero_kernel() {
    g_hist[blockIdx.x * blockDim.x + threadIdx.x] = 0;
}

// Fused: blocks [0, HISTBLK) build the histogram, blocks [HISTBLK, ...) repack tables.
__global__ void __launch_bounds__(256)
hist_repack_kernel(const float2* __restrict__ uv, const float2* __restrict__ lat)
{
    if (blockIdx.x < HISTBLK) {
        __shared__ int s_h[NBINS];
        int tid = threadIdx.x;
#pragma unroll
        for (int i = 0; i < NBINS / 256; i++) s_h[tid + i * 256] = 0;
        __syncthreads();

        const float4* uv4 = (const float4*)uv;   // 2 points per float4
        int base4 = blockIdx.x * 2048;           // 4096 points per block
#pragma unroll
        for (int i = 0; i < 8; i++) {
            float4 q = __ldg(&uv4[base4 + i * 256 + tid]);
            atomicAdd(&s_h[bin_of(q.x, q.y)], 1);
            atomicAdd(&s_h[bin_of(q.z, q.w)], 1);
        }
        __syncthreads();

#pragma unroll
        for (int i = 0; i < NBINS / 256; i++) {
            int b = tid + i * 256;
            int c = s_h[b];
            if (c) atomicAdd(&g_hist[b], c);
        }
        return;
    }

    int c = (blockIdx.x - HISTBLK) * 256 + threadIdx.x;
    if (c >= RPTOTAL) return;

    if (c >= QTOTAL) {
        int base = (c - QTOTAL) * 4;
        __half2 h0 = sc_h2(lat[HBASE + base + 0]);
        __half2 h1 = sc_h2(lat[HBASE + base + 1]);
        __half2 h2 = sc_h2(lat[HBASE + base + 2]);
        __half2 h3 = sc_h2(lat[HBASE + base + 3]);
        float4 v;
        ((__half2*)&v)[0] = h0; ((__half2*)&v)[1] = h1;
        ((__half2*)&v)[2] = h2; ((__half2*)&v)[3] = h3;
        *(float4*)(g_hh + base) = v;
        return;
    }

    int l = 0;
#pragma unroll
    for (int i = 1; i < 12; i++) l += (c >= c_qoff[i]);

    int local = c - c_qoff[l];
    int res   = c_res[l];
    int x     = local / res;
    int y     = local - x * res;
    int base  = c_off[l] + x * res + y;

    __half2 h00 = sc_h2(lat[base]);
    __half2 h01 = sc_h2(lat[base + 1]);
    __half2 h10 = sc_h2(lat[base + res]);
    __half2 h11 = sc_h2(lat[base + res + 1]);

    float4 v;
    ((__half2*)&v)[0] = h00; ((__half2*)&v)[1] = h01;
    ((__half2*)&v)[2] = h10; ((__half2*)&v)[3] = h11;
    *(float4*)(g_qh + (size_t)c * 4) = v;
}

// 1024-bin exclusive scan + zero g_fill.
__global__ void __launch_bounds__(NBINS)
scan_kernel() {
    __shared__ int s[NBINS];
    int t = threadIdx.x;
    int h = g_hist[t];
    s[t] = h;
    __syncthreads();
#pragma unroll
    for (int off = 1; off < NBINS; off <<= 1) {
        int v = (t >= off) ? s[t - off] : 0;
        __syncthreads();
        s[t] += v;
        __syncthreads();
    }
    g_binbase[t] = s[t] - h;   // exclusive prefix
    g_fill[t] = 0;
}

// 512 blocks x 512 threads x 4 points: smem ranks, aggregated global adds with
// folded binbase, one packed 16B store per point. 8KB smem -> 3 blocks/SM.
__global__ void __launch_bounds__(512)
scatter_kernel(const float2* __restrict__ uv)
{
    __shared__ int s_cnt[NBINS];
    __shared__ int s_off[NBINS];
    int tid = threadIdx.x;
#pragma unroll
    for (int i = 0; i < NBINS / 512; i++) s_cnt[tid + i * 512] = 0;
    __syncthreads();

    const float4* uv4 = (const float4*)uv;
    int base4 = blockIdx.x * 1024;           // 2048 points per block
    float4 qa = __ldg(&uv4[base4 + tid]);
    float4 qb = __ldg(&uv4[base4 + 512 + tid]);

    int b0 = bin_of(qa.x, qa.y);
    int b1 = bin_of(qa.z, qa.w);
    int b2 = bin_of(qb.x, qb.y);
    int b3 = bin_of(qb.z, qb.w);
    int r0 = atomicAdd(&s_cnt[b0], 1);
    int r1 = atomicAdd(&s_cnt[b1], 1);
    int r2 = atomicAdd(&s_cnt[b2], 1);
    int r3 = atomicAdd(&s_cnt[b3], 1);
    __syncthreads();

#pragma unroll
    for (int i = 0; i < NBINS / 512; i++) {
        int b = tid + i * 512;
        int c = s_cnt[b];
        int f = c ? atomicAdd(&g_fill[b], c) : 0;
        s_off[b] = g_binbase[b] + f;
    }
    __syncthreads();

    int na = (base4 + tid) * 2;
    int nb = (base4 + 512 + tid) * 2;
    g_uvp[s_off[b0] + r0] = make_float4(qa.x, qa.y, __int_as_float(na), 0.0f);
    g_uvp[s_off[b1] + r1] = make_float4(qa.z, qa.w, __int_as_float(na + 1), 0.0f);
    g_uvp[s_off[b2] + r2] = make_float4(qb.x, qb.y, __int_as_float(nb), 0.0f);
    g_uvp[s_off[b3] + r3] = make_float4(qb.z, qb.w, __int_as_float(nb + 1), 0.0f);
}

__global__ void __launch_bounds__(256)
hashgrid2d_kernel(float4* __restrict__ out)
{
    __shared__ float2 s_uv[32];
    __shared__ int    s_pn[32];
    __shared__ float4 s_tr[256];

    int tid = threadIdx.x;
    int w   = tid >> 5;          // slot: levels {2w, 2w+1}
    int ln  = tid & 31;
    int n0  = blockIdx.x * 32;

    if (w == 0) {
        float4 q = g_uvp[n0 + ln];
        s_uv[ln] = make_float2(q.x, q.y);
        s_pn[ln] = __float_as_int(q.z);
    }
    __syncthreads();
    float2 p = s_uv[ln];

    float r0, r1, r2, r3;

    if (w < 6) {
        // ---- two dense levels: one 16B quad load each ----
        float rr[4];
#pragma unroll
        for (int k = 0; k < 2; k++) {
            int l   = 2 * w + k;
            int res = c_res[l];

            float fres = (float)res;
            float sx = p.x * fres;
            float sy = p.y * fres;
            float fx = floorf(sx);
            float fy = floorf(sy);
            int   x0 = (int)fx;
            int   y0 = (int)fy;
            float px = sx - fx;
            float py = sy - fy;

            float4 raw = *(const float4*)(g_qh + (size_t)(c_qoff[l] + x0 * res + y0) * 4);
            const __half2* h = (const __half2*)&raw;
            float2 v00 = __half22float2(h[0]);
            float2 v01 = __half22float2(h[1]);
            float2 v10 = __half22float2(h[2]);
            float2 v11 = __half22float2(h[3]);

            float qx = 1.0f - px;
            float qy = 1.0f - py;
            float w00 = qx * qy;
            float w01 = qx * py;
            float w10 = px * qy;
            float w11 = px * py;

            rr[2 * k + 0] = v00.x * w00 + v01.x * w01 + v10.x * w10 + v11.x * w11;
            rr[2 * k + 1] = v00.y * w00 + v01.y * w01 + v10.y * w10 + v11.y * w11;
        }
        r0 = rr[0]; r1 = rr[1]; r2 = rr[2]; r3 = rr[3];
    } else {
        // ---- two hashed levels: 16B group-of-4 loads + weight scatter ----
        float rr[4];
#pragma unroll
        for (int k = 0; k < 2; k++) {
            int l = 12 + (w - 6) * 2 + k;

            float fres = (float)c_res[l];
            float sx = p.x * fres;
            float sy = p.y * fres;
            float fx = floorf(sx);
            float fy = floorf(sy);
            int   x0 = (int)fx;
            int   y0 = (int)fy;
            float px = sx - fx;
            float py = sy - fy;

            float qx = 1.0f - px;
            float qy = 1.0f - py;

            const __half2* H = g_hh + (size_t)(l - 12) * TSIZE;

            int hy0 = y0 * HPRIME;
            int hy1 = hy0 + HPRIME;
            int i0  = (x0 ^ hy0) & TMASK;
            int i1  = (x0 ^ hy1) & TMASK;

            float4 raw0 = *(const float4*)(H + (i0 & ~3));
            float4 raw1 = *(const float4*)(H + (i1 & ~3));
            const __half2* v0 = (const __half2*)&raw0;
            const __half2* v1 = (const __half2*)&raw1;

            int  d   = ((x0 + 1) ^ x0) & 3;        // 1 or 3
            bool ing = (x0 & 3) != 3;              // x0+1 in same 16B group?
            float wpx = ing ? px : 0.0f;

            int pA0 = i0 & 3, pB0 = pA0 ^ d;
            int pA1 = i1 & 3, pB1 = pA1 ^ d;

            float e0x = 0.f, e0y = 0.f, e1x = 0.f, e1y = 0.f;
#pragma unroll
            for (int t = 0; t < 4; t++) {
                float wt0 = (t == pA0) ? qx : ((t == pB0) ? wpx : 0.0f);
                float wt1 = (t == pA1) ? qx : ((t == pB1) ? wpx : 0.0f);
                float2 a = __half22float2(v0[t]);
                float2 b = __half22float2(v1[t]);
                e0x += wt0 * a.x; e0y += wt0 * a.y;
                e1x += wt1 * b.x; e1y += wt1 * b.y;
            }

            if (!ing) {
                int x1 = x0 + 1;
                float2 f0 = __half22float2(H[(x1 ^ hy0) & TMASK]);
                float2 f1 = __half22float2(H[(x1 ^ hy1) & TMASK]);
                e0x += px * f0.x; e0y += px * f0.y;
                e1x += px * f1.x; e1y += px * f1.y;
            }

            rr[2 * k + 0] = qy * e0x + py * e1x;
            rr[2 * k + 1] = qy * e0y + py * e1y;
        }
        r0 = rr[0]; r1 = rr[1]; r2 = rr[2]; r3 = rr[3];
    }

    r0 *= INV_SCALE_F; r1 *= INV_SCALE_F; r2 *= INV_SCALE_F; r3 *= INV_SCALE_F;

    // XOR-swizzled transpose; store to each point's ORIGINAL slot (one 128B
    // line per point -> same wavefront count as a coalesced store).
    s_tr[ln * 8 + (w ^ (ln & 7))] = make_float4(r0, r1, r2, r3);
    __syncthreads();

    int jj = tid & 7;
    int ll = tid >> 3;
    int pn = s_pn[ll];
    out[(size_t)pn * 8 + jj] = s_tr[ll * 8 + (jj ^ (ll & 7))];
}

extern "C" void kernel_launch(void* const* d_in, const int* in_sizes, int n_in,
                              void* d_out, int out_size)
{
    const float2* uv  = (const float2*)d_in[0];
    const float2* lat = (const float2*)d_in[1];
    float4*       out = (float4*)d_out;

    zero_kernel<<<NBINS / 256, 256>>>();
    hist_repack_kernel<<<HISTBLK + RPBLK, 256>>>(uv, lat);
    scan_kernel<<<1, NBINS>>>();
    scatter_kernel<<<SCTBLK, 512>>>(uv);

    hashgrid2d_kernel<<<NPTS / 32, 256>>>(out);
}

// round 12
// speedup vs baseline: 1.1197x; 1.1072x over previous
#include <cuda_runtime.h>
#include <cuda_fp16.h>

// HashGridEncoder2D: L=16, F=2, N=1048576, T=524288. fp16 tables scaled by 4096.
// R12: single-kernel BLOCK-LOCAL counting sort (8192 pts/block, 32x32 bins,
// smem hist + shuffle scan + smem record scatter, coalesced output) fused with
// the table repack. Main gather kernel = R11 staged slot-warp form.

#define NPTS    1048576
#define TSIZE   524288
#define TMASK   (TSIZE - 1)
#define HPRIME  131101
#define QTOTAL  659835                 // sum of res^2 over dense levels 0..11
#define HBASE   663817                 // float2 index where hashed tables start
#define RPTOTAL (QTOTAL + TSIZE)
#define RPBLK   ((RPTOTAL + 1023) / 1024)
#define NBINS   1024
#define SORTBLK 128                    // sort blocks (8192 points each)
#define PPB     8192                   // points per sort block
#define SCALE_F     4096.0f
#define INV_SCALE_F (1.0f / 4096.0f)

// dynamic smem layout for sort blocks:
//   float su[8192] | float sv[8192] | int sp[8192] | int s_cnt[1024] | int s_base[1024] | int s_wt[32]
#define SMEMSZ (PPB * 12 + NBINS * 8 + 128)

__constant__ int c_res[16] = {16, 22, 30, 42, 58, 80, 111, 153,
                              212, 294, 406, 561, 776, 1072, 1482, 2048};
__constant__ int c_off[16] = {0, 289, 818, 1779, 3628, 7109, 13670, 26214,
                              49930, 95299, 182324, 347973,
                              663817, 1188105, 1712393, 2236681};
__constant__ int c_qoff[12] = {0, 256, 740, 1640, 3404, 6768, 13168,
                               25489, 48898, 93842, 180278, 345114};

// 10.6 MB: dense cell (l,x,y) -> {v00,v01,v10,v11} as 4 half2 (16B aligned).
__device__ __align__(16) __half2 g_qh[(size_t)QTOTAL * 4];
// 8.4 MB: 16B-aligned fp16 mirror of the 4 hashed level tables.
__device__ __align__(16) __half2 g_hh[4 * TSIZE];
// sorted records {u, v, perm-as-int, 0}
__device__ __align__(16) float4 g_uvp[NPTS];

__device__ __forceinline__ __half2 sc_h2(float2 v) {
    return __floats2half2_rn(v.x * SCALE_F, v.y * SCALE_F);
}

__device__ __forceinline__ int bin_of(float px, float py) {
    int kx = min((int)(px * 32.0f), 31);
    int ky = min((int)(py * 32.0f), 31);
    return ky * 32 + kx;
}

// Fused: blocks [0, SORTBLK) block-local sort; blocks [SORTBLK, ...) repack.
__global__ void __launch_bounds__(1024)
sort_repack_kernel(const float2* __restrict__ uv, const float2* __restrict__ lat)
{
    extern __shared__ char dynsmem[];

    int tid = threadIdx.x;

    if (blockIdx.x < SORTBLK) {
        float* su     = (float*)dynsmem;
        float* sv     = su + PPB;
        int*   sp     = (int*)(sv + PPB);
        int*   s_cnt  = sp + PPB;
        int*   s_base = s_cnt + NBINS;
        int*   s_wt   = s_base + NBINS;

        s_cnt[tid] = 0;
        __syncthreads();

        // phase 1: load 8 points, bin, rank via smem atomics
        const float4* uv4 = (const float4*)uv;
        int base4 = blockIdx.x * (PPB / 2);
        float4 q[4];
        int    bn[8], rk[8];
#pragma unroll
        for (int j = 0; j < 4; j++) {
            q[j] = __ldg(&uv4[base4 + j * 1024 + tid]);
            bn[2 * j]     = bin_of(q[j].x, q[j].y);
            bn[2 * j + 1] = bin_of(q[j].z, q[j].w);
            rk[2 * j]     = atomicAdd(&s_cnt[bn[2 * j]], 1);
            rk[2 * j + 1] = atomicAdd(&s_cnt[bn[2 * j + 1]], 1);
        }
        __syncthreads();

        // phase 2: exclusive scan of 1024 bin counts (shuffle-based)
        int c = s_cnt[tid];
        int lane = tid & 31, wid = tid >> 5;
        int incl = c;
#pragma unroll
        for (int off = 1; off < 32; off <<= 1) {
            int v = __shfl_up_sync(0xffffffffu, incl, off);
            if (lane >= off) incl += v;
        }
        if (lane == 31) s_wt[wid] = incl;
        __syncthreads();
        if (wid == 0) {
            int wv = s_wt[lane];
            int wi = wv;
#pragma unroll
            for (int off = 1; off < 32; off <<= 1) {
                int v = __shfl_up_sync(0xffffffffu, wi, off);
                if (lane >= off) wi += v;
            }
            s_wt[lane] = wi - wv;   // exclusive warp offsets
        }
        __syncthreads();
        s_base[tid] = s_wt[wid] + incl - c;   // exclusive bin base
        __syncthreads();

        // phase 3: scatter records into sorted smem positions
#pragma unroll
        for (int j = 0; j < 4; j++) {
            int n0 = (base4 + j * 1024 + tid) * 2;
            int p0 = s_base[bn[2 * j]] + rk[2 * j];
            int p1 = s_base[bn[2 * j + 1]] + rk[2 * j + 1];
            su[p0] = q[j].x; sv[p0] = q[j].y; sp[p0] = n0;
            su[p1] = q[j].z; sv[p1] = q[j].w; sp[p1] = n0 + 1;
        }
        __syncthreads();

        // phase 4: coalesced write of sorted records
        int gbase = blockIdx.x * PPB;
#pragma unroll
        for (int j = 0; j < 8; j++) {
            int i = j * 1024 + tid;
            g_uvp[gbase + i] = make_float4(su[i], sv[i],
                                           __int_as_float(sp[i]), 0.0f);
        }
        return;
    }

    // ---- repack blocks ----
    int c = (blockIdx.x - SORTBLK) * 1024 + tid;
    if (c >= RPTOTAL) return;

    if (c >= QTOTAL) {
        int base = (c - QTOTAL) * 4;
        __half2 h0 = sc_h2(lat[HBASE + base + 0]);
        __half2 h1 = sc_h2(lat[HBASE + base + 1]);
        __half2 h2 = sc_h2(lat[HBASE + base + 2]);
        __half2 h3 = sc_h2(lat[HBASE + base + 3]);
        float4 v;
        ((__half2*)&v)[0] = h0; ((__half2*)&v)[1] = h1;
        ((__half2*)&v)[2] = h2; ((__half2*)&v)[3] = h3;
        *(float4*)(g_hh + base) = v;
        return;
    }

    int l = 0;
#pragma unroll
    for (int i = 1; i < 12; i++) l += (c >= c_qoff[i]);

    int local = c - c_qoff[l];
    int res   = c_res[l];
    int x     = local / res;
    int y     = local - x * res;
    int base  = c_off[l] + x * res + y;

    __half2 h00 = sc_h2(lat[base]);
    __half2 h01 = sc_h2(lat[base + 1]);
    __half2 h10 = sc_h2(lat[base + res]);
    __half2 h11 = sc_h2(lat[base + res + 1]);

    float4 v;
    ((__half2*)&v)[0] = h00; ((__half2*)&v)[1] = h01;
    ((__half2*)&v)[2] = h10; ((__half2*)&v)[3] = h11;
    *(float4*)(g_qh + (size_t)c * 4) = v;
}

__global__ void __launch_bounds__(256)
hashgrid2d_kernel(float4* __restrict__ out)
{
    __shared__ float2 s_uv[32];
    __shared__ int    s_pn[32];
    __shared__ float4 s_tr[256];

    int tid = threadIdx.x;
    int w   = tid >> 5;          // slot: levels {2w, 2w+1}
    int ln  = tid & 31;
    int n0  = blockIdx.x * 32;

    if (w == 0) {
        float4 q = g_uvp[n0 + ln];
        s_uv[ln] = make_float2(q.x, q.y);
        s_pn[ln] = __float_as_int(q.z);
    }
    __syncthreads();
    float2 p = s_uv[ln];

    float r0, r1, r2, r3;

    if (w < 6) {
        // ---- two dense levels: one 16B quad load each ----
        float rr[4];
#pragma unroll
        for (int k = 0; k < 2; k++) {
            int l   = 2 * w + k;
            int res = c_res[l];

            float fres = (float)res;
            float sx = p.x * fres;
            float sy = p.y * fres;
            float fx = floorf(sx);
            float fy = floorf(sy);
            int   x0 = (int)fx;
            int   y0 = (int)fy;
            float px = sx - fx;
            float py = sy - fy;

            float4 raw = *(const float4*)(g_qh + (size_t)(c_qoff[l] + x0 * res + y0) * 4);
            const __half2* h = (const __half2*)&raw;
            float2 v00 = __half22float2(h[0]);
            float2 v01 = __half22float2(h[1]);
            float2 v10 = __half22float2(h[2]);
            float2 v11 = __half22float2(h[3]);

            float qx = 1.0f - px;
            float qy = 1.0f - py;
            float w00 = qx * qy;
            float w01 = qx * py;
            float w10 = px * qy;
            float w11 = px * py;

            rr[2 * k + 0] = v00.x * w00 + v01.x * w01 + v10.x * w10 + v11.x * w11;
            rr[2 * k + 1] = v00.y * w00 + v01.y * w01 + v10.y * w10 + v11.y * w11;
        }
        r0 = rr[0]; r1 = rr[1]; r2 = rr[2]; r3 = rr[3];
    } else {
        // ---- two hashed levels: 16B group-of-4 loads + weight scatter ----
        float rr[4];
#pragma unroll
        for (int k = 0; k < 2; k++) {
            int l = 12 + (w - 6) * 2 + k;

            float fres = (float)c_res[l];
            float sx = p.x * fres;
            float sy = p.y * fres;
            float fx = floorf(sx);
            float fy = floorf(sy);
            int   x0 = (int)fx;
            int   y0 = (int)fy;
            float px = sx - fx;
            float py = sy - fy;

            float qx = 1.0f - px;
            float qy = 1.0f - py;

            const __half2* H = g_hh + (size_t)(l - 12) * TSIZE;

            int hy0 = y0 * HPRIME;
            int hy1 = hy0 + HPRIME;
            int i0  = (x0 ^ hy0) & TMASK;
            int i1  = (x0 ^ hy1) & TMASK;

            float4 raw0 = *(const float4*)(H + (i0 & ~3));
            float4 raw1 = *(const float4*)(H + (i1 & ~3));
            const __half2* v0 = (const __half2*)&raw0;
            const __half2* v1 = (const __half2*)&raw1;

            int  d   = ((x0 + 1) ^ x0) & 3;        // 1 or 3
            bool ing = (x0 & 3) != 3;              // x0+1 in same 16B group?
            float wpx = ing ? px : 0.0f;

            int pA0 = i0 & 3, pB0 = pA0 ^ d;
            int pA1 = i1 & 3, pB1 = pA1 ^ d;

            float e0x = 0.f, e0y = 0.f, e1x = 0.f, e1y = 0.f;
#pragma unroll
            for (int t = 0; t < 4; t++) {
                float wt0 = (t == pA0) ? qx : ((t == pB0) ? wpx : 0.0f);
                float wt1 = (t == pA1) ? qx : ((t == pB1) ? wpx : 0.0f);
                float2 a = __half22float2(v0[t]);
                float2 b = __half22float2(v1[t]);
                e0x += wt0 * a.x; e0y += wt0 * a.y;
                e1x += wt1 * b.x; e1y += wt1 * b.y;
            }

            if (!ing) {
                int x1 = x0 + 1;
                float2 f0 = __half22float2(H[(x1 ^ hy0) & TMASK]);
                float2 f1 = __half22float2(H[(x1 ^ hy1) & TMASK]);
                e0x += px * f0.x; e0y += px * f0.y;
                e1x += px * f1.x; e1y += px * f1.y;
            }

            rr[2 * k + 0] = qy * e0x + py * e1x;
            rr[2 * k + 1] = qy * e0y + py * e1y;
        }
        r0 = rr[0]; r1 = rr[1]; r2 = rr[2]; r3 = rr[3];
    }

    r0 *= INV_SCALE_F; r1 *= INV_SCALE_F; r2 *= INV_SCALE_F; r3 *= INV_SCALE_F;

    // XOR-swizzled transpose; store to each point's ORIGINAL slot (one 128B
    // line per point -> same wavefront count as a coalesced store).
    s_tr[ln * 8 + (w ^ (ln & 7))] = make_float4(r0, r1, r2, r3);
    __syncthreads();

    int jj = tid & 7;
    int ll = tid >> 3;
    int pn = s_pn[ll];
    out[(size_t)pn * 8 + jj] = s_tr[ll * 8 + (jj ^ (ll & 7))];
}

extern "C" void kernel_launch(void* const* d_in, const int* in_sizes, int n_in,
                              void* d_out, int out_size)
{
    const float2* uv  = (const float2*)d_in[0];
    const float2* lat = (const float2*)d_in[1];
    float4*       out = (float4*)d_out;

    static int smem_set = 0;
    // cudaFuncSetAttribute is idempotent and not a stream operation; calling it
    // unconditionally keeps kernel_launch deterministic and capture-safe.
    cudaFuncSetAttribute(sort_repack_kernel,
                         cudaFuncAttributeMaxDynamicSharedMemorySize, SMEMSZ);
    (void)smem_set;

    sort_repack_kernel<<<SORTBLK + RPBLK, 1024, SMEMSZ>>>(uv, lat);

    hashgrid2d_kernel<<<NPTS / 32, 256>>>(out);
}

// round 13
// speedup vs baseline: 1.1644x; 1.0400x over previous
#include <cuda_runtime.h>
#include <cuda_fp16.h>

// HashGridEncoder2D: L=16, F=2, N=1048576, T=524288. fp16 tables scaled by 4096.
// R13: hashed path uses direct value-select (3-SEL tree) instead of 4-slot
// weight scatter; block-local sort shrunk to 4096 pts/block (2 blocks/SM).
// Levels 0..11 dense: 16B quad LDG. Levels 12..15 hashed: 16B group-of-4.

#define NPTS    1048576
#define TSIZE   524288
#define TMASK   (TSIZE - 1)
#define HPRIME  131101
#define QTOTAL  659835                 // sum of res^2 over dense levels 0..11
#define HBASE   663817                 // float2 index where hashed tables start
#define RPTOTAL (QTOTAL + TSIZE)
#define RPBLK   ((RPTOTAL + 1023) / 1024)
#define NBINS   1024
#define SORTBLK 256                    // sort blocks (4096 points each)
#define PPB     4096                   // points per sort block
#define SCALE_F     4096.0f
#define INV_SCALE_F (1.0f / 4096.0f)

// dynamic smem for sort blocks:
// float su[PPB] | float sv[PPB] | int sp[PPB] | int s_cnt[NBINS] | int s_base[NBINS] | int s_wt[32]
#define SMEMSZ (PPB * 12 + NBINS * 8 + 128)

__constant__ int c_res[16] = {16, 22, 30, 42, 58, 80, 111, 153,
                              212, 294, 406, 561, 776, 1072, 1482, 2048};
__constant__ int c_off[16] = {0, 289, 818, 1779, 3628, 7109, 13670, 26214,
                              49930, 95299, 182324, 347973,
                              663817, 1188105, 1712393, 2236681};
__constant__ int c_qoff[12] = {0, 256, 740, 1640, 3404, 6768, 13168,
                               25489, 48898, 93842, 180278, 345114};

// 10.6 MB: dense cell (l,x,y) -> {v00,v01,v10,v11} as 4 half2 (16B aligned).
__device__ __align__(16) __half2 g_qh[(size_t)QTOTAL * 4];
// 8.4 MB: 16B-aligned fp16 mirror of the 4 hashed level tables.
__device__ __align__(16) __half2 g_hh[4 * TSIZE];
// sorted records {u, v, perm-as-int, 0}
__device__ __align__(16) float4 g_uvp[NPTS];

__device__ __forceinline__ __half2 sc_h2(float2 v) {
    return __floats2half2_rn(v.x * SCALE_F, v.y * SCALE_F);
}

__device__ __forceinline__ int bin_of(float px, float py) {
    int kx = min((int)(px * 32.0f), 31);
    int ky = min((int)(py * 32.0f), 31);
    return ky * 32 + kx;
}

// select one of 4 half2 regs with a 3-SEL tree
__device__ __forceinline__ __half2 sel4(const __half2* v, int s) {
    __half2 t0 = (s & 1) ? v[1] : v[0];
    __half2 t1 = (s & 1) ? v[3] : v[2];
    return (s & 2) ? t1 : t0;
}

// Fused: blocks [0, SORTBLK) block-local sort; blocks [SORTBLK, ...) repack.
__global__ void __launch_bounds__(1024)
sort_repack_kernel(const float2* __restrict__ uv, const float2* __restrict__ lat)
{
    extern __shared__ char dynsmem[];

    int tid = threadIdx.x;

    if (blockIdx.x < SORTBLK) {
        float* su     = (float*)dynsmem;
        float* sv     = su + PPB;
        int*   sp     = (int*)(sv + PPB);
        int*   s_cnt  = sp + PPB;
        int*   s_base = s_cnt + NBINS;
        int*   s_wt   = s_base + NBINS;

        s_cnt[tid] = 0;
        __syncthreads();

        // phase 1: load 4 points, bin, rank via smem atomics
        const float4* uv4 = (const float4*)uv;
        int base4 = blockIdx.x * (PPB / 2);
        float4 q[2];
        int    bn[4], rk[4];
#pragma unroll
        for (int j = 0; j < 2; j++) {
            q[j] = __ldg(&uv4[base4 + j * 1024 + tid]);
            bn[2 * j]     = bin_of(q[j].x, q[j].y);
            bn[2 * j + 1] = bin_of(q[j].z, q[j].w);
            rk[2 * j]     = atomicAdd(&s_cnt[bn[2 * j]], 1);
            rk[2 * j + 1] = atomicAdd(&s_cnt[bn[2 * j + 1]], 1);
        }
        __syncthreads();

        // phase 2: exclusive scan of 1024 bin counts (shuffle-based)
        int c = s_cnt[tid];
        int lane = tid & 31, wid = tid >> 5;
        int incl = c;
#pragma unroll
        for (int off = 1; off < 32; off <<= 1) {
            int v = __shfl_up_sync(0xffffffffu, incl, off);
            if (lane >= off) incl += v;
        }
        if (lane == 31) s_wt[wid] = incl;
        __syncthreads();
        if (wid == 0) {
            int wv = s_wt[lane];
            int wi = wv;
#pragma unroll
            for (int off = 1; off < 32; off <<= 1) {
                int v = __shfl_up_sync(0xffffffffu, wi, off);
                if (lane >= off) wi += v;
            }
            s_wt[lane] = wi - wv;   // exclusive warp offsets
        }
        __syncthreads();
        s_base[tid] = s_wt[wid] + incl - c;   // exclusive bin base
        __syncthreads();

        // phase 3: scatter records into sorted smem positions
#pragma unroll
        for (int j = 0; j < 2; j++) {
            int n0 = (base4 + j * 1024 + tid) * 2;
            int p0 = s_base[bn[2 * j]] + rk[2 * j];
            int p1 = s_base[bn[2 * j + 1]] + rk[2 * j + 1];
            su[p0] = q[j].x; sv[p0] = q[j].y; sp[p0] = n0;
            su[p1] = q[j].z; sv[p1] = q[j].w; sp[p1] = n0 + 1;
        }
        __syncthreads();

        // phase 4: coalesced write of sorted records
        int gbase = blockIdx.x * PPB;
#pragma unroll
        for (int j = 0; j < 4; j++) {
            int i = j * 1024 + tid;
            g_uvp[gbase + i] = make_float4(su[i], sv[i],
                                           __int_as_float(sp[i]), 0.0f);
        }
        return;
    }

    // ---- repack blocks ----
    int c = (blockIdx.x - SORTBLK) * 1024 + tid;
    if (c >= RPTOTAL) return;

    if (c >= QTOTAL) {
        int base = (c - QTOTAL) * 4;
        __half2 h0 = sc_h2(lat[HBASE + base + 0]);
        __half2 h1 = sc_h2(lat[HBASE + base + 1]);
        __half2 h2 = sc_h2(lat[HBASE + base + 2]);
        __half2 h3 = sc_h2(lat[HBASE + base + 3]);
        float4 v;
        ((__half2*)&v)[0] = h0; ((__half2*)&v)[1] = h1;
        ((__half2*)&v)[2] = h2; ((__half2*)&v)[3] = h3;
        *(float4*)(g_hh + base) = v;
        return;
    }

    int l = 0;
#pragma unroll
    for (int i = 1; i < 12; i++) l += (c >= c_qoff[i]);

    int local = c - c_qoff[l];
    int res   = c_res[l];
    int x     = local / res;
    int y     = local - x * res;
    int base  = c_off[l] + x * res + y;

    __half2 h00 = sc_h2(lat[base]);
    __half2 h01 = sc_h2(lat[base + 1]);
    __half2 h10 = sc_h2(lat[base + res]);
    __half2 h11 = sc_h2(lat[base + res + 1]);

    float4 v;
    ((__half2*)&v)[0] = h00; ((__half2*)&v)[1] = h01;
    ((__half2*)&v)[2] = h10; ((__half2*)&v)[3] = h11;
    *(float4*)(g_qh + (size_t)c * 4) = v;
}

__global__ void __launch_bounds__(256)
hashgrid2d_kernel(float4* __restrict__ out)
{
    __shared__ float2 s_uv[32];
    __shared__ int    s_pn[32];
    __shared__ float4 s_tr[256];

    int tid = threadIdx.x;
    int w   = tid >> 5;          // slot: levels {2w, 2w+1}
    int ln  = tid & 31;
    int n0  = blockIdx.x * 32;

    if (w == 0) {
        float4 q = g_uvp[n0 + ln];
        s_uv[ln] = make_float2(q.x, q.y);
        s_pn[ln] = __float_as_int(q.z);
    }
    __syncthreads();
    float2 p = s_uv[ln];

    float r0, r1, r2, r3;

    if (w < 6) {
        // ---- two dense levels: one 16B quad load each ----
        float rr[4];
#pragma unroll
        for (int k = 0; k < 2; k++) {
            int l   = 2 * w + k;
            int res = c_res[l];

            float fres = (float)res;
            float sx = p.x * fres;
            float sy = p.y * fres;
            float fx = floorf(sx);
            float fy = floorf(sy);
            int   x0 = (int)fx;
            int   y0 = (int)fy;
            float px = sx - fx;
            float py = sy - fy;

            float4 raw = *(const float4*)(g_qh + (size_t)(c_qoff[l] + x0 * res + y0) * 4);
            const __half2* h = (const __half2*)&raw;
            float2 v00 = __half22float2(h[0]);
            float2 v01 = __half22float2(h[1]);
            float2 v10 = __half22float2(h[2]);
            float2 v11 = __half22float2(h[3]);

            float qx = 1.0f - px;
            float qy = 1.0f - py;
            float w00 = qx * qy;
            float w01 = qx * py;
            float w10 = px * qy;
            float w11 = px * py;

            rr[2 * k + 0] = v00.x * w00 + v01.x * w01 + v10.x * w10 + v11.x * w11;
            rr[2 * k + 1] = v00.y * w00 + v01.y * w01 + v10.y * w10 + v11.y * w11;
        }
        r0 = rr[0]; r1 = rr[1]; r2 = rr[2]; r3 = rr[3];
    } else {
        // ---- two hashed levels: group-of-4 loads + direct value select ----
        float rr[4];
#pragma unroll
        for (int k = 0; k < 2; k++) {
            int l = 12 + (w - 6) * 2 + k;

            float fres = (float)c_res[l];
            float sx = p.x * fres;
            float sy = p.y * fres;
            float fx = floorf(sx);
            float fy = floorf(sy);
            int   x0 = (int)fx;
            int   y0 = (int)fy;
            float px = sx - fx;
            float py = sy - fy;

            float qx = 1.0f - px;
            float qy = 1.0f - py;

            const __half2* H = g_hh + (size_t)(l - 12) * TSIZE;

            int hy0 = y0 * HPRIME;
            int hy1 = hy0 + HPRIME;
            int i0  = (x0 ^ hy0) & TMASK;
            int i1  = (x0 ^ hy1) & TMASK;

            float4 raw0 = *(const float4*)(H + (i0 & ~3));
            float4 raw1 = *(const float4*)(H + (i1 & ~3));
            const __half2* v0 = (const __half2*)&raw0;
            const __half2* v1 = (const __half2*)&raw1;

            int  d   = ((x0 + 1) ^ x0) & 3;        // 1 or 3
            int  pA0 = i0 & 3, pA1 = i1 & 3;

            __half2 a0 = sel4(v0, pA0);            // x0 corner, row y0
            __half2 a1 = sel4(v1, pA1);            // x0 corner, row y0+1
            __half2 b0 = sel4(v0, pA0 ^ d);        // x0+1 corner (if in-group)
            __half2 b1 = sel4(v1, pA1 ^ d);

            if ((x0 & 3) == 3) {                   // partner outside the group
                int x1 = x0 + 1;
                b0 = H[(x1 ^ hy0) & TMASK];
                b1 = H[(x1 ^ hy1) & TMASK];
            }

            float2 A0 = __half22float2(a0);
            float2 B0 = __half22float2(b0);
            float2 A1 = __half22float2(a1);
            float2 B1 = __half22float2(b1);

            float ex0 = qx * A0.x + px * B0.x;
            float ey0 = qx * A0.y + px * B0.y;
            float ex1 = qx * A1.x + px * B1.x;
            float ey1 = qx * A1.y + px * B1.y;

            rr[2 * k + 0] = qy * ex0 + py * ex1;
            rr[2 * k + 1] = qy * ey0 + py * ey1;
        }
        r0 = rr[0]; r1 = rr[1]; r2 = rr[2]; r3 = rr[3];
    }

    r0 *= INV_SCALE_F; r1 *= INV_SCALE_F; r2 *= INV_SCALE_F; r3 *= INV_SCALE_F;

    // XOR-swizzled transpose; store to each point's ORIGINAL slot (one 128B
    // line per point -> same wavefront count as a coalesced store).
    s_tr[ln * 8 + (w ^ (ln & 7))] = make_float4(r0, r1, r2, r3);
    __syncthreads();

    int jj = tid & 7;
    int ll = tid >> 3;
    int pn = s_pn[ll];
    out[(size_t)pn * 8 + jj] = s_tr[ll * 8 + (jj ^ (ll & 7))];
}

extern "C" void kernel_launch(void* const* d_in, const int* in_sizes, int n_in,
                              void* d_out, int out_size)
{
    const float2* uv  = (const float2*)d_in[0];
    const float2* lat = (const float2*)d_in[1];
    float4*       out = (float4*)d_out;

    // idempotent, not a stream op -> capture-safe
    cudaFuncSetAttribute(sort_repack_kernel,
                         cudaFuncAttributeMaxDynamicSharedMemorySize, SMEMSZ);

    sort_repack_kernel<<<SORTBLK + RPBLK, 1024, SMEMSZ>>>(uv, lat);

    hashgrid2d_kernel<<<NPTS / 32, 256>>>(out);
}